// round 1
// baseline (speedup 1.0000x reference)
#include <cuda_runtime.h>

// Problem constants
#define BB   512
#define TT   65536
#define CL   128                 // chunk length
#define NC   (TT / CL)           // 512 chunks per row
#define NTH  256
#define GRID ((BB * NC) / NTH)   // 1024 blocks

// Scratch (static __device__ arrays -- no allocation)
__device__ __align__(16) float g_y1[(size_t)BB * TT];       // forward-pass output (128 MB)
__device__ __align__(16) float g_v[(size_t)BB * NC * 8];    // per-chunk zero-state final states
__device__ float g_coef[17];    // [0..8]=b/a0, [9..16]=-(a[1..8]/a0)
__device__ float g_M[64];       // A^CL
__device__ float g_M2[64];      // A^(2*CL)

// ---------------------------------------------------------------------------
// Setup: normalize coefficients, build M = A^CL and M^2. One block, 64 threads.
// A is the homogeneous DF2T state map: z'[i] = z[i+1] - a[i+1]*z[0], z[8]=0.
// ---------------------------------------------------------------------------
__global__ void setup_kernel(const float* __restrict__ b, const float* __restrict__ a) {
    __shared__ float sa[9];
    __shared__ float sM[64];
    int tid = threadIdx.x;
    if (tid == 0) {
        float inv = 1.0f / a[0];
        #pragma unroll
        for (int i = 0; i < 9; i++) {
            float bn = b[i] * inv;
            float an = a[i] * inv;
            g_coef[i] = bn;
            if (i >= 1) g_coef[8 + i] = -an;
            sa[i] = an;
        }
    }
    __syncthreads();
    if (tid < 8) {
        float s[9];
        #pragma unroll
        for (int i = 0; i < 9; i++) s[i] = 0.0f;
        s[tid] = 1.0f;
        for (int step = 0; step < CL; step++) {
            float y = s[0];
            #pragma unroll
            for (int i = 0; i < 8; i++) s[i] = s[i + 1] - sa[i + 1] * y;
            // s[8] stays 0
        }
        #pragma unroll
        for (int i = 0; i < 8; i++) { sM[i * 8 + tid] = s[i]; g_M[i * 8 + tid] = s[i]; }
    }
    __syncthreads();
    if (tid < 64) {
        int i = tid >> 3, j = tid & 7;
        float acc = 0.0f;
        #pragma unroll
        for (int k = 0; k < 8; k++) acc = fmaf(sM[i * 8 + k], sM[k * 8 + j], acc);
        g_M2[tid] = acc;
    }
}

// One DF2T step. Ascending z updates read old z[i+1] before it is overwritten.
#define IIR_STEP(xv) do {                                  \
    float y_ = fmaf(cb0, (xv), z0);                        \
    z0 = fmaf(cna1, y_, fmaf(cb1, (xv), z1));              \
    z1 = fmaf(cna2, y_, fmaf(cb2, (xv), z2));              \
    z2 = fmaf(cna3, y_, fmaf(cb3, (xv), z3));              \
    z3 = fmaf(cna4, y_, fmaf(cb4, (xv), z4));              \
    z4 = fmaf(cna5, y_, fmaf(cb5, (xv), z5));              \
    z5 = fmaf(cna6, y_, fmaf(cb6, (xv), z6));              \
    z6 = fmaf(cna7, y_, fmaf(cb7, (xv), z7));              \
    z7 = fmaf(cna8, y_, cb8 * (xv));                       \
} while (0)

#define IIR_STEP_Y(xv, yout) do {                          \
    float y_ = fmaf(cb0, (xv), z0);                        \
    (yout) = y_;                                           \
    z0 = fmaf(cna1, y_, fmaf(cb1, (xv), z1));              \
    z1 = fmaf(cna2, y_, fmaf(cb2, (xv), z2));              \
    z2 = fmaf(cna3, y_, fmaf(cb3, (xv), z3));              \
    z3 = fmaf(cna4, y_, fmaf(cb4, (xv), z4));              \
    z4 = fmaf(cna5, y_, fmaf(cb5, (xv), z5));              \
    z5 = fmaf(cna6, y_, fmaf(cb6, (xv), z6));              \
    z6 = fmaf(cna7, y_, fmaf(cb7, (xv), z7));              \
    z7 = fmaf(cna8, y_, cb8 * (xv));                       \
} while (0)

#define LOAD_COEF()                                        \
    float cb0  = g_coef[0],  cb1  = g_coef[1],             \
          cb2  = g_coef[2],  cb3  = g_coef[3],             \
          cb4  = g_coef[4],  cb5  = g_coef[5],             \
          cb6  = g_coef[6],  cb7  = g_coef[7],             \
          cb8  = g_coef[8];                                \
    float cna1 = g_coef[9],  cna2 = g_coef[10],            \
          cna3 = g_coef[11], cna4 = g_coef[12],            \
          cna5 = g_coef[13], cna6 = g_coef[14],            \
          cna7 = g_coef[15], cna8 = g_coef[16];

// ---------------------------------------------------------------------------
// Pass A: zero-state chunk filtering; emit only the final 8-dim state.
// DIR=0: forward in time. DIR=1: reversed traversal of the input rows.
// ---------------------------------------------------------------------------
template <int DIR>
__global__ void __launch_bounds__(NTH) pass_state(const float* __restrict__ in,
                                                  float* __restrict__ vout) {
    int tid = blockIdx.x * NTH + threadIdx.x;
    int r = tid / NC;
    int c = tid - r * NC;
    LOAD_COEF();
    float z0 = 0.f, z1 = 0.f, z2 = 0.f, z3 = 0.f, z4 = 0.f, z5 = 0.f, z6 = 0.f, z7 = 0.f;
    const float* row = in + (size_t)r * TT;
    int s0 = c * CL;
    #pragma unroll 2
    for (int t = 0; t < CL; t += 4) {
        float xa, xb, xc, xd;
        if (DIR == 0) {
            float4 x4 = *reinterpret_cast<const float4*>(row + s0 + t);
            xa = x4.x; xb = x4.y; xc = x4.z; xd = x4.w;
        } else {
            float4 x4 = *reinterpret_cast<const float4*>(row + (TT - 4 - (s0 + t)));
            xa = x4.w; xb = x4.z; xc = x4.y; xd = x4.x;
        }
        IIR_STEP(xa); IIR_STEP(xb); IIR_STEP(xc); IIR_STEP(xd);
    }
    float* vp = vout + (size_t)tid * 8;
    vp[0] = z0; vp[1] = z1; vp[2] = z2; vp[3] = z3;
    vp[4] = z4; vp[5] = z5; vp[6] = z6; vp[7] = z7;
}

// ---------------------------------------------------------------------------
// Pass C: seed chunk-start state via 3-term lookback (v[c-1] + M v[c-2] + M^2 v[c-3]),
// re-run the chunk, write y.
// ---------------------------------------------------------------------------
template <int DIR>
__global__ void __launch_bounds__(NTH) pass_out(const float* __restrict__ in,
                                                float* __restrict__ out,
                                                const float* __restrict__ vin) {
    __shared__ float sM[64];
    __shared__ float sM2[64];
    if (threadIdx.x < 64) sM[threadIdx.x] = g_M[threadIdx.x];
    else if (threadIdx.x < 128) sM2[threadIdx.x - 64] = g_M2[threadIdx.x - 64];
    __syncthreads();

    int tid = blockIdx.x * NTH + threadIdx.x;
    int r = tid / NC;
    int c = tid - r * NC;

    // Lookback state reconstruction
    float v1[8], v2[8], v3[8];
    #pragma unroll
    for (int i = 0; i < 8; i++) { v1[i] = 0.f; v2[i] = 0.f; v3[i] = 0.f; }
    const float* vb = vin + ((size_t)r * NC) * 8;
    if (c >= 1) {
        #pragma unroll
        for (int i = 0; i < 8; i++) v1[i] = vb[(c - 1) * 8 + i];
    }
    if (c >= 2) {
        #pragma unroll
        for (int i = 0; i < 8; i++) v2[i] = vb[(c - 2) * 8 + i];
    }
    if (c >= 3) {
        #pragma unroll
        for (int i = 0; i < 8; i++) v3[i] = vb[(c - 3) * 8 + i];
    }
    float s[8];
    #pragma unroll
    for (int i = 0; i < 8; i++) {
        float acc = v1[i];
        #pragma unroll
        for (int j = 0; j < 8; j++) acc = fmaf(sM[i * 8 + j], v2[j], acc);
        #pragma unroll
        for (int j = 0; j < 8; j++) acc = fmaf(sM2[i * 8 + j], v3[j], acc);
        s[i] = acc;
    }

    LOAD_COEF();
    float z0 = s[0], z1 = s[1], z2 = s[2], z3 = s[3],
          z4 = s[4], z5 = s[5], z6 = s[6], z7 = s[7];

    const float* row  = in  + (size_t)r * TT;
    float*       rowo = out + (size_t)r * TT;
    int sbase = c * CL;
    #pragma unroll 2
    for (int t = 0; t < CL; t += 4) {
        float xa, xb, xc, xd;
        if (DIR == 0) {
            float4 x4 = *reinterpret_cast<const float4*>(row + sbase + t);
            xa = x4.x; xb = x4.y; xc = x4.z; xd = x4.w;
        } else {
            float4 x4 = *reinterpret_cast<const float4*>(row + (TT - 4 - (sbase + t)));
            xa = x4.w; xb = x4.z; xc = x4.y; xd = x4.x;
        }
        float y0, y1v, y2v, y3v;
        IIR_STEP_Y(xa, y0);
        IIR_STEP_Y(xb, y1v);
        IIR_STEP_Y(xc, y2v);
        IIR_STEP_Y(xd, y3v);
        float4 o;
        if (DIR == 0) {
            o.x = y0; o.y = y1v; o.z = y2v; o.w = y3v;
            *reinterpret_cast<float4*>(rowo + sbase + t) = o;
        } else {
            // logical sample s -> original index TT-1-s; group stored at TT-4-s
            o.x = y3v; o.y = y2v; o.z = y1v; o.w = y0;
            *reinterpret_cast<float4*>(rowo + (TT - 4 - (sbase + t))) = o;
        }
    }
}

extern "C" void kernel_launch(void* const* d_in, const int* in_sizes, int n_in,
                              void* d_out, int out_size) {
    const float* x = (const float*)d_in[0];
    const float* b = (const float*)d_in[1];
    const float* a = (const float*)d_in[2];
    float* out = (float*)d_out;

    float* py1 = nullptr;
    float* pv  = nullptr;
    cudaGetSymbolAddress((void**)&py1, g_y1);
    cudaGetSymbolAddress((void**)&pv,  g_v);

    setup_kernel<<<1, 64>>>(b, a);
    // Forward direction: x -> g_y1
    pass_state<0><<<GRID, NTH>>>(x, pv);
    pass_out<0><<<GRID, NTH>>>(x, py1, pv);
    // Backward direction: reversed(g_y1) filtered, written back reversed -> d_out
    pass_state<1><<<GRID, NTH>>>(py1, pv);
    pass_out<1><<<GRID, NTH>>>(py1, out, pv);
}

// round 2
// speedup vs baseline: 1.1504x; 1.1504x over previous
#include <cuda_runtime.h>

// Problem constants
#define BB   512
#define TT   65536
#define CL   128                 // chunk length
#define NC   (TT / CL)           // 512 chunks per row
#define NTH  256
#define RPG  128                 // rows per launch group
#define NGRP (BB / RPG)          // 4 groups
#define GRIDB (RPG * 2)          // 256 blocks per launch (2 half-rows per row)
#define SMEM_OUT (2 * NTH * 9 * 16)   // two padded float4 buffers = 73728 B

// Scratch (static __device__ arrays -- no allocation)
__device__ __align__(16) float g_y1[(size_t)BB * TT];     // forward-pass output (128 MB)
__device__ __align__(16) float g_v[(size_t)BB * NC * 8];  // per-chunk zero-state final states
__device__ float g_coef[17];   // [0..8]=b/a0, [9..16]=-(a[1..8]/a0)
__device__ float g_M[64];      // A^CL
__device__ float g_M2[64];     // A^(2*CL)

// ---------------------------------------------------------------------------
// Setup: normalize coefficients, build M = A^CL and M^2.
// ---------------------------------------------------------------------------
__global__ void setup_kernel(const float* __restrict__ b, const float* __restrict__ a) {
    __shared__ float sa[9];
    __shared__ float sM[64];
    int tid = threadIdx.x;
    if (tid == 0) {
        float inv = 1.0f / a[0];
        #pragma unroll
        for (int i = 0; i < 9; i++) {
            float bn = b[i] * inv;
            float an = a[i] * inv;
            g_coef[i] = bn;
            if (i >= 1) g_coef[8 + i] = -an;
            sa[i] = an;
        }
    }
    __syncthreads();
    if (tid < 8) {
        float s[9];
        #pragma unroll
        for (int i = 0; i < 9; i++) s[i] = 0.0f;
        s[tid] = 1.0f;
        for (int step = 0; step < CL; step++) {
            float y = s[0];
            #pragma unroll
            for (int i = 0; i < 8; i++) s[i] = s[i + 1] - sa[i + 1] * y;
        }
        #pragma unroll
        for (int i = 0; i < 8; i++) { sM[i * 8 + tid] = s[i]; g_M[i * 8 + tid] = s[i]; }
    }
    __syncthreads();
    if (tid < 64) {
        int i = tid >> 3, j = tid & 7;
        float acc = 0.0f;
        #pragma unroll
        for (int k = 0; k < 8; k++) acc = fmaf(sM[i * 8 + k], sM[k * 8 + j], acc);
        g_M2[tid] = acc;
    }
}

#define IIR_STEP(xv) do {                                  \
    float y_ = fmaf(cb0, (xv), z0);                        \
    z0 = fmaf(cna1, y_, fmaf(cb1, (xv), z1));              \
    z1 = fmaf(cna2, y_, fmaf(cb2, (xv), z2));              \
    z2 = fmaf(cna3, y_, fmaf(cb3, (xv), z3));              \
    z3 = fmaf(cna4, y_, fmaf(cb4, (xv), z4));              \
    z4 = fmaf(cna5, y_, fmaf(cb5, (xv), z5));              \
    z5 = fmaf(cna6, y_, fmaf(cb6, (xv), z6));              \
    z6 = fmaf(cna7, y_, fmaf(cb7, (xv), z7));              \
    z7 = fmaf(cna8, y_, cb8 * (xv));                       \
} while (0)

#define IIR_STEP_Y(xv, yout) do {                          \
    float y_ = fmaf(cb0, (xv), z0);                        \
    (yout) = y_;                                           \
    z0 = fmaf(cna1, y_, fmaf(cb1, (xv), z1));              \
    z1 = fmaf(cna2, y_, fmaf(cb2, (xv), z2));              \
    z2 = fmaf(cna3, y_, fmaf(cb3, (xv), z3));              \
    z3 = fmaf(cna4, y_, fmaf(cb4, (xv), z4));              \
    z4 = fmaf(cna5, y_, fmaf(cb5, (xv), z5));              \
    z5 = fmaf(cna6, y_, fmaf(cb6, (xv), z6));              \
    z6 = fmaf(cna7, y_, fmaf(cb7, (xv), z7));              \
    z7 = fmaf(cna8, y_, cb8 * (xv));                       \
} while (0)

#define LOAD_COEF()                                        \
    float cb0  = g_coef[0],  cb1  = g_coef[1],             \
          cb2  = g_coef[2],  cb3  = g_coef[3],             \
          cb4  = g_coef[4],  cb5  = g_coef[5],             \
          cb6  = g_coef[6],  cb7  = g_coef[7],             \
          cb8  = g_coef[8];                                \
    float cna1 = g_coef[9],  cna2 = g_coef[10],            \
          cna3 = g_coef[11], cna4 = g_coef[12],            \
          cna5 = g_coef[13], cna6 = g_coef[14],            \
          cna7 = g_coef[15], cna8 = g_coef[16];

// Gmem float-index of the stage-s slice start for staging-thread tt (DIR aware).
// DIR=0: chunks ascend; DIR=1: logical chunk data sits at descending physical addrs.
template <int DIR>
__device__ __forceinline__ int slice_base(int h, int tt, int s) {
    if (DIR == 0) return h * 32768 + tt * CL + s * 32;
    return TT - (h * 256 + tt + 1) * CL + (3 - s) * 32;
}

// ---------------------------------------------------------------------------
// Pass A: zero-state chunk filtering via smem-staged coalesced loads;
// emit only the 8-dim final state per chunk.
// ---------------------------------------------------------------------------
template <int DIR>
__global__ void __launch_bounds__(NTH) pass_state(const float* __restrict__ in,
                                                  float* __restrict__ vout, int row0) {
    __shared__ float4 sb[NTH * 9];
    int row = row0 + (blockIdx.x >> 1);
    int h = blockIdx.x & 1;
    int t = threadIdx.x;
    int c = h * 256 + t;
    LOAD_COEF();
    float z0 = 0.f, z1 = 0.f, z2 = 0.f, z3 = 0.f, z4 = 0.f, z5 = 0.f, z6 = 0.f, z7 = 0.f;
    const float* rowp = in + (size_t)row * TT;

    #pragma unroll 1
    for (int s = 0; s < 4; s++) {
        // Cooperative coalesced load: 8 consecutive lanes cover one 128B slice.
        #pragma unroll
        for (int l = 0; l < 8; l++) {
            int q = l * NTH + t;
            int tq = q >> 3, j = q & 7;
            int tt = (DIR == 0) ? tq : 255 - tq;
            int base = slice_base<DIR>(h, tt, s);
            sb[tt * 9 + j] = *reinterpret_cast<const float4*>(rowp + base + 4 * j);
        }
        __syncthreads();
        #pragma unroll
        for (int j2 = 0; j2 < 8; j2++) {
            if (DIR == 0) {
                float4 x4 = sb[t * 9 + j2];
                IIR_STEP(x4.x); IIR_STEP(x4.y); IIR_STEP(x4.z); IIR_STEP(x4.w);
            } else {
                float4 x4 = sb[t * 9 + (7 - j2)];
                IIR_STEP(x4.w); IIR_STEP(x4.z); IIR_STEP(x4.y); IIR_STEP(x4.x);
            }
        }
        __syncthreads();
    }
    float4* vp = reinterpret_cast<float4*>(vout + ((size_t)row * NC + c) * 8);
    vp[0] = make_float4(z0, z1, z2, z3);
    vp[1] = make_float4(z4, z5, z6, z7);
}

// ---------------------------------------------------------------------------
// Pass C: seed chunk-start state via 3-term lookback, re-run chunk, write y.
// Both input and output staged through smem for coalescing.
// ---------------------------------------------------------------------------
template <int DIR>
__global__ void __launch_bounds__(NTH) pass_out(const float* __restrict__ in,
                                                float* __restrict__ out,
                                                const float* __restrict__ vin, int row0) {
    extern __shared__ float4 db[];
    float4* bin = db;
    float4* bo  = db + NTH * 9;

    int row = row0 + (blockIdx.x >> 1);
    int h = blockIdx.x & 1;
    int t = threadIdx.x;
    int c = h * 256 + t;

    // Lookback state reconstruction: S = v[c-1] + M v[c-2] + M^2 v[c-3]
    float v1[8], v2[8], v3[8];
    #pragma unroll
    for (int i = 0; i < 8; i++) { v1[i] = 0.f; v2[i] = 0.f; v3[i] = 0.f; }
    const float* vb = vin + ((size_t)row * NC) * 8;
    if (c >= 1) {
        #pragma unroll
        for (int i = 0; i < 8; i++) v1[i] = vb[(c - 1) * 8 + i];
    }
    if (c >= 2) {
        #pragma unroll
        for (int i = 0; i < 8; i++) v2[i] = vb[(c - 2) * 8 + i];
    }
    if (c >= 3) {
        #pragma unroll
        for (int i = 0; i < 8; i++) v3[i] = vb[(c - 3) * 8 + i];
    }
    float sst[8];
    #pragma unroll
    for (int i = 0; i < 8; i++) {
        float acc = v1[i];
        #pragma unroll
        for (int j = 0; j < 8; j++) acc = fmaf(g_M[i * 8 + j], v2[j], acc);
        #pragma unroll
        for (int j = 0; j < 8; j++) acc = fmaf(g_M2[i * 8 + j], v3[j], acc);
        sst[i] = acc;
    }

    LOAD_COEF();
    float z0 = sst[0], z1 = sst[1], z2 = sst[2], z3 = sst[3],
          z4 = sst[4], z5 = sst[5], z6 = sst[6], z7 = sst[7];

    const float* rowp = in  + (size_t)row * TT;
    float*       rowo = out + (size_t)row * TT;

    #pragma unroll 1
    for (int s = 0; s < 4; s++) {
        // Coalesced load into bin
        #pragma unroll
        for (int l = 0; l < 8; l++) {
            int q = l * NTH + t;
            int tq = q >> 3, j = q & 7;
            int tt = (DIR == 0) ? tq : 255 - tq;
            int base = slice_base<DIR>(h, tt, s);
            bin[tt * 9 + j] = *reinterpret_cast<const float4*>(rowp + base + 4 * j);
        }
        __syncthreads();
        // Consume bin, produce into bo (physical layout)
        #pragma unroll
        for (int j2 = 0; j2 < 8; j2++) {
            if (DIR == 0) {
                float4 x4 = bin[t * 9 + j2];
                float y0, y1v, y2v, y3v;
                IIR_STEP_Y(x4.x, y0);
                IIR_STEP_Y(x4.y, y1v);
                IIR_STEP_Y(x4.z, y2v);
                IIR_STEP_Y(x4.w, y3v);
                bo[t * 9 + j2] = make_float4(y0, y1v, y2v, y3v);
            } else {
                float4 x4 = bin[t * 9 + (7 - j2)];
                float y0, y1v, y2v, y3v;
                IIR_STEP_Y(x4.w, y0);
                IIR_STEP_Y(x4.z, y1v);
                IIR_STEP_Y(x4.y, y2v);
                IIR_STEP_Y(x4.x, y3v);
                bo[t * 9 + (7 - j2)] = make_float4(y3v, y2v, y1v, y0);
            }
        }
        __syncthreads();
        // Coalesced store from bo (same address mapping as the load)
        #pragma unroll
        for (int l = 0; l < 8; l++) {
            int q = l * NTH + t;
            int tq = q >> 3, j = q & 7;
            int tt = (DIR == 0) ? tq : 255 - tq;
            int base = slice_base<DIR>(h, tt, s);
            *reinterpret_cast<float4*>(rowo + base + 4 * j) = bo[tt * 9 + j];
        }
        // next-stage load into bin is fenced by the post-load __syncthreads
    }
}

extern "C" void kernel_launch(void* const* d_in, const int* in_sizes, int n_in,
                              void* d_out, int out_size) {
    const float* x = (const float*)d_in[0];
    const float* b = (const float*)d_in[1];
    const float* a = (const float*)d_in[2];
    float* out = (float*)d_out;

    float* py1 = nullptr;
    float* pv  = nullptr;
    cudaGetSymbolAddress((void**)&py1, g_y1);
    cudaGetSymbolAddress((void**)&pv,  g_v);

    static bool attr_done = false;
    if (!attr_done) {
        cudaFuncSetAttribute(pass_out<0>, cudaFuncAttributeMaxDynamicSharedMemorySize, SMEM_OUT);
        cudaFuncSetAttribute(pass_out<1>, cudaFuncAttributeMaxDynamicSharedMemorySize, SMEM_OUT);
        attr_done = true;
    }

    setup_kernel<<<1, 64>>>(b, a);
    // Group-pipelined: keep each 128-row group's x / y1 / out resident in L2
    // across its four passes.
    for (int g = 0; g < NGRP; g++) {
        int row0 = g * RPG;
        pass_state<0><<<GRIDB, NTH>>>(x, pv, row0);
        pass_out<0><<<GRIDB, NTH, SMEM_OUT>>>(x, py1, pv, row0);
        pass_state<1><<<GRIDB, NTH>>>(py1, pv, row0);
        pass_out<1><<<GRIDB, NTH, SMEM_OUT>>>(py1, out, pv, row0);
    }
}